// round 10
// baseline (speedup 1.0000x reference)
#include <cuda_runtime.h>
#include <cuda_fp16.h>

#define NN 50000
#define NE 800000
#define NG 256
#define F  64

// ---------------- scratch ----------------
__device__ __align__(16) __half g_hh[NN * F];   // h * dinv[src], fp16 (gather payload)
__device__ __align__(16) float g_agg[NN * F];   // self-loop init, then full agg (fp32)
__device__ __align__(16) float g_sums[NG * F];
__device__ float g_cnt[NG];
__device__ float g_dinv[NN];
__device__ float g_invdeg[NN];
__device__ int   g_deg[NN];
__device__ int   g_rowstart[NN];
__device__ int   g_cursor[NN];
__device__ int   g_counter;
__device__ int   g_ssorted[NE];

__device__ __forceinline__ void red_add_v4(float* p, float4 v) {
    asm volatile("red.global.add.v4.f32 [%0], {%1, %2, %3, %4};"
                 :: "l"(p), "f"(v.x), "f"(v.y), "f"(v.z), "f"(v.w) : "memory");
}

// ---------------- prep kernels ----------------
__global__ void zero_kernel() {
    int i = blockIdx.x * blockDim.x + threadIdx.x;
    if (i < NG * F) g_sums[i] = 0.0f;
    if (i < NG) g_cnt[i] = 0.0f;
    if (i == 0) g_counter = 0;
}

__global__ void deg_kernel(const int* __restrict__ dst) {
    int e = blockIdx.x * blockDim.x + threadIdx.x;
    if (e < NE) atomicAdd(&g_deg[dst[e]], 1);
}

// Fused: dinv/invdeg/cnt + block-local scan + block-atomic region placement.
__global__ void scan_fused_kernel(const int* __restrict__ batch) {
    __shared__ int s[2][256];
    __shared__ int blockoff;
    int tid = threadIdx.x;
    int i = blockIdx.x * 256 + tid;
    int v = (i < NN) ? g_deg[i] : 0;
    s[0][tid] = v;
    if (i < NN) {
        float d = (float)(v + 1);
        g_dinv[i] = rsqrtf(d);
        g_invdeg[i] = 1.0f / d;
        atomicAdd(&g_cnt[batch[i]], 1.0f);
    }
    __syncthreads();
    int cur = 0;
#pragma unroll
    for (int off = 1; off < 256; off <<= 1) {
        int val = s[cur][tid];
        if (tid >= off) val += s[cur][tid - off];
        s[cur ^ 1][tid] = val;
        cur ^= 1;
        __syncthreads();
    }
    if (tid == 0) blockoff = atomicAdd(&g_counter, s[cur][255]);
    __syncthreads();
    int excl = (tid == 0) ? 0 : s[cur][tid - 1];
    if (i < NN) {
        int rs = excl + blockoff;
        g_rowstart[i] = rs;
        g_cursor[i] = rs;
    }
}

__global__ void scatter_kernel(const int* __restrict__ src, const int* __restrict__ dst) {
    int e = blockIdx.x * blockDim.x + threadIdx.x;
    if (e < NE) {
        int d = dst[e];
        int pos = atomicAdd(&g_cursor[d], 1);
        g_ssorted[pos] = src[e];
    }
}

// ---------------- GEMM + self-loop init (4 rows x 16 cols/thread) ----
// in = (FIRST ? x : relu(g_agg + b_prev)); a = in @ W
// g_hh = half(a * dinv); g_agg = a * invdeg
// Block: 128 threads = 32 quads x 4 parts; 128 nodes/block.
// __launch_bounds__(128, 5): cap regs ~102 -> 5 blocks (20 warps)/SM.
template <bool FIRST>
__global__ __launch_bounds__(128, 5) void gemm_kernel(const float* __restrict__ x,
                                                      const float* __restrict__ W,
                                                      const float* __restrict__ bprev) {
    __shared__ float4 Ws[F * 16];
    int tid = threadIdx.x;
    const float4* W4 = (const float4*)W;
#pragma unroll
    for (int i = tid; i < F * 16; i += 128) Ws[i] = W4[i];
    __syncthreads();

    int part = tid & 3;
    int quad = tid >> 2;
    int base = blockIdx.x * 128 + quad * 4;

    const float4* in4 = FIRST ? (const float4*)x : (const float4*)g_agg;
    const float4* b4 = (const float4*)bprev;

    float4 acc[4][4];
#pragma unroll
    for (int r = 0; r < 4; ++r)
#pragma unroll
        for (int j = 0; j < 4; ++j) acc[r][j] = make_float4(0.f, 0.f, 0.f, 0.f);

#pragma unroll
    for (int k4 = 0; k4 < 16; ++k4) {
        float4 bv;
        if (!FIRST) bv = b4[k4];
        float xs[4][4];
#pragma unroll
        for (int r = 0; r < 4; ++r) {
            int node = base + r;
            float4 xv = make_float4(0.f, 0.f, 0.f, 0.f);
            if (node < NN) {
                xv = in4[(size_t)node * 16 + k4];
                if (!FIRST) {
                    xv.x = fmaxf(xv.x + bv.x, 0.f);
                    xv.y = fmaxf(xv.y + bv.y, 0.f);
                    xv.z = fmaxf(xv.z + bv.z, 0.f);
                    xv.w = fmaxf(xv.w + bv.w, 0.f);
                }
            }
            xs[r][0] = xv.x; xs[r][1] = xv.y; xs[r][2] = xv.z; xs[r][3] = xv.w;
        }
#pragma unroll
        for (int kk = 0; kk < 4; ++kk) {
            const float4* wrow = &Ws[(k4 * 4 + kk) * 16 + part * 4];
            float4 w0 = wrow[0], w1 = wrow[1], w2 = wrow[2], w3 = wrow[3];
#pragma unroll
            for (int r = 0; r < 4; ++r) {
                float v = xs[r][kk];
                acc[r][0].x = fmaf(v, w0.x, acc[r][0].x);
                acc[r][0].y = fmaf(v, w0.y, acc[r][0].y);
                acc[r][0].z = fmaf(v, w0.z, acc[r][0].z);
                acc[r][0].w = fmaf(v, w0.w, acc[r][0].w);
                acc[r][1].x = fmaf(v, w1.x, acc[r][1].x);
                acc[r][1].y = fmaf(v, w1.y, acc[r][1].y);
                acc[r][1].z = fmaf(v, w1.z, acc[r][1].z);
                acc[r][1].w = fmaf(v, w1.w, acc[r][1].w);
                acc[r][2].x = fmaf(v, w2.x, acc[r][2].x);
                acc[r][2].y = fmaf(v, w2.y, acc[r][2].y);
                acc[r][2].z = fmaf(v, w2.z, acc[r][2].z);
                acc[r][2].w = fmaf(v, w2.w, acc[r][2].w);
                acc[r][3].x = fmaf(v, w3.x, acc[r][3].x);
                acc[r][3].y = fmaf(v, w3.y, acc[r][3].y);
                acc[r][3].z = fmaf(v, w3.z, acc[r][3].z);
                acc[r][3].w = fmaf(v, w3.w, acc[r][3].w);
            }
        }
    }

#pragma unroll
    for (int r = 0; r < 4; ++r) {
        int node = base + r;
        if (node >= NN) continue;
        float dv = g_dinv[node];
        float id = g_invdeg[node];
        __half2* hr = (__half2*)(g_hh + (size_t)node * F + part * 16);
        float4* ar = (float4*)(g_agg + (size_t)node * F) + part * 4;
#pragma unroll
        for (int j = 0; j < 4; ++j) {
            float4 a = acc[r][j];
            hr[j * 2 + 0] = __floats2half2_rn(a.x * dv, a.y * dv);
            hr[j * 2 + 1] = __floats2half2_rn(a.z * dv, a.w * dv);
            ar[j] = make_float4(a.x * id, a.y * id, a.z * id, a.w * id);
        }
    }
}

// ---------------- CSR aggregation: 8-lane group per dst, fp16 gather, MLP=4 ----
template <bool LAST>
__global__ __launch_bounds__(256) void agg_kernel(const int* __restrict__ batch,
                                                  const float* __restrict__ b3) {
    int t = blockIdx.x * blockDim.x + threadIdx.x;
    int d = t >> 3;
    int l = t & 7;            // 8 lanes x 8 features (16B) per lane
    if (d >= NN) return;
    int start = g_rowstart[d];
    int n = g_deg[d];
    const uint4* h4 = (const uint4*)g_hh;   // one uint4 = 8 halfs

    float acc[8];
#pragma unroll
    for (int j = 0; j < 8; ++j) acc[j] = 0.f;

    int i = 0;
    for (; i + 4 <= n; i += 4) {
        int s0 = g_ssorted[start + i];
        int s1 = g_ssorted[start + i + 1];
        int s2 = g_ssorted[start + i + 2];
        int s3 = g_ssorted[start + i + 3];
        uint4 r0 = h4[(size_t)s0 * 8 + l];
        uint4 r1 = h4[(size_t)s1 * 8 + l];
        uint4 r2 = h4[(size_t)s2 * 8 + l];
        uint4 r3 = h4[(size_t)s3 * 8 + l];
        const __half2* p0 = (const __half2*)&r0;
        const __half2* p1 = (const __half2*)&r1;
        const __half2* p2 = (const __half2*)&r2;
        const __half2* p3 = (const __half2*)&r3;
#pragma unroll
        for (int j = 0; j < 4; ++j) {
            float2 f0 = __half22float2(p0[j]);
            float2 f1 = __half22float2(p1[j]);
            float2 f2 = __half22float2(p2[j]);
            float2 f3 = __half22float2(p3[j]);
            acc[j * 2 + 0] += (f0.x + f1.x) + (f2.x + f3.x);
            acc[j * 2 + 1] += (f0.y + f1.y) + (f2.y + f3.y);
        }
    }
    for (; i < n; ++i) {
        int s0 = g_ssorted[start + i];
        uint4 r0 = h4[(size_t)s0 * 8 + l];
        const __half2* p0 = (const __half2*)&r0;
#pragma unroll
        for (int j = 0; j < 4; ++j) {
            float2 f0 = __half22float2(p0[j]);
            acc[j * 2 + 0] += f0.x;
            acc[j * 2 + 1] += f0.y;
        }
    }

    float dd = g_dinv[d];
    float4* ar = (float4*)(g_agg + (size_t)d * F + l * 8);
    float4 s0v = ar[0];
    float4 s1v = ar[1];
    float4 o0 = make_float4(fmaf(acc[0], dd, s0v.x), fmaf(acc[1], dd, s0v.y),
                            fmaf(acc[2], dd, s0v.z), fmaf(acc[3], dd, s0v.w));
    float4 o1 = make_float4(fmaf(acc[4], dd, s1v.x), fmaf(acc[5], dd, s1v.y),
                            fmaf(acc[6], dd, s1v.z), fmaf(acc[7], dd, s1v.w));
    if (!LAST) {
        ar[0] = o0;
        ar[1] = o1;
    } else {
        float4 b0 = ((const float4*)b3)[l * 2 + 0];
        float4 b1 = ((const float4*)b3)[l * 2 + 1];
        o0.x = fmaxf(o0.x + b0.x, 0.f); o0.y = fmaxf(o0.y + b0.y, 0.f);
        o0.z = fmaxf(o0.z + b0.z, 0.f); o0.w = fmaxf(o0.w + b0.w, 0.f);
        o1.x = fmaxf(o1.x + b1.x, 0.f); o1.y = fmaxf(o1.y + b1.y, 0.f);
        o1.z = fmaxf(o1.z + b1.z, 0.f); o1.w = fmaxf(o1.w + b1.w, 0.f);
        int g = batch[d];
        red_add_v4(g_sums + (size_t)g * F + l * 8, o0);
        red_add_v4(g_sums + (size_t)g * F + l * 8 + 4, o1);
    }
}

// out[g] = (sums[g] . Wl) / max(cnt,1) + bl
__global__ void final_kernel(const float* __restrict__ Wl, const float* __restrict__ bl,
                             float* __restrict__ out) {
    int g = threadIdx.x;
    float c = fmaxf(g_cnt[g], 1.0f);
    float acc = 0.f;
#pragma unroll
    for (int f = 0; f < F; ++f) acc = fmaf(g_sums[g * F + f], Wl[f], acc);
    out[g] = acc / c + bl[0];
}

// ---------------- launch ----------------
extern "C" void kernel_launch(void* const* d_in, const int* in_sizes, int n_in,
                              void* d_out, int out_size) {
    const float* x   = (const float*)d_in[0];
    const int* src   = (const int*)d_in[1];
    const int* dst   = (const int*)d_in[2];
    const int* batch = (const int*)d_in[3];
    const float* W1 = (const float*)d_in[4];
    const float* b1 = (const float*)d_in[5];
    const float* W2 = (const float*)d_in[6];
    const float* b2 = (const float*)d_in[7];
    const float* W3 = (const float*)d_in[8];
    const float* b3 = (const float*)d_in[9];
    const float* Wl = (const float*)d_in[10];
    const float* bl = (const float*)d_in[11];
    float* out = (float*)d_out;

    const int NB_NODE = (NN + 255) / 256;        // 196
    const int NB_EDGE = (NE + 255) / 256;        // 3125
    const int NB_GEMM = (NN + 127) / 128;        // 391
    const int NB_AGG  = (NN * 8 + 255) / 256;    // 1563
    const int NB_ZERO = (NG * F + 255) / 256;    // 64

    void* deg_ptr = nullptr;
    cudaGetSymbolAddress(&deg_ptr, g_deg);
    cudaMemsetAsync(deg_ptr, 0, NN * sizeof(int));

    zero_kernel<<<NB_ZERO, 256>>>();
    deg_kernel<<<NB_EDGE, 256>>>(dst);
    scan_fused_kernel<<<NB_NODE, 256>>>(batch);
    scatter_kernel<<<NB_EDGE, 256>>>(src, dst);

    // layer 1
    gemm_kernel<true><<<NB_GEMM, 128>>>(x, W1, nullptr);
    agg_kernel<false><<<NB_AGG, 256>>>(batch, b3);
    // layer 2
    gemm_kernel<false><<<NB_GEMM, 128>>>(nullptr, W2, b1);
    agg_kernel<false><<<NB_AGG, 256>>>(batch, b3);
    // layer 3 (+ fused pool)
    gemm_kernel<false><<<NB_GEMM, 128>>>(nullptr, W3, b2);
    agg_kernel<true><<<NB_AGG, 256>>>(batch, b3);

    final_kernel<<<1, 256>>>(Wl, bl, out);
}

// round 11
// speedup vs baseline: 1.2623x; 1.2623x over previous
#include <cuda_runtime.h>
#include <cuda_fp16.h>

#define NN 50000
#define NE 800000
#define NG 256
#define F  64

// ---------------- scratch ----------------
__device__ __align__(16) __half g_hh[NN * F];   // h * dinv[src], fp16 (gather payload)
__device__ __align__(16) float g_agg[NN * F];   // self-loop init, then full agg (fp32)
__device__ __align__(16) float g_sums[NG * F];
__device__ float g_cnt[NG];
__device__ float g_dinv[NN];
__device__ float g_invdeg[NN];
__device__ int   g_deg[NN];
__device__ int   g_rowstart[NN];
__device__ int   g_cursor[NN];
__device__ int   g_counter;
__device__ int   g_ssorted[NE];

__device__ __forceinline__ void red_add_v4(float* p, float4 v) {
    asm volatile("red.global.add.v4.f32 [%0], {%1, %2, %3, %4};"
                 :: "l"(p), "f"(v.x), "f"(v.y), "f"(v.z), "f"(v.w) : "memory");
}

// ---------------- prep kernels ----------------
__global__ void zero_kernel() {
    int i = blockIdx.x * blockDim.x + threadIdx.x;
    if (i < NG * F) g_sums[i] = 0.0f;
    if (i < NG) g_cnt[i] = 0.0f;
    if (i == 0) g_counter = 0;
}

__global__ void deg_kernel(const int* __restrict__ dst) {
    int e = blockIdx.x * blockDim.x + threadIdx.x;
    if (e < NE) atomicAdd(&g_deg[dst[e]], 1);
}

// Fused: dinv/invdeg/cnt + block-local scan + block-atomic region placement.
__global__ void scan_fused_kernel(const int* __restrict__ batch) {
    __shared__ int s[2][256];
    __shared__ int blockoff;
    int tid = threadIdx.x;
    int i = blockIdx.x * 256 + tid;
    int v = (i < NN) ? g_deg[i] : 0;
    s[0][tid] = v;
    if (i < NN) {
        float d = (float)(v + 1);
        g_dinv[i] = rsqrtf(d);
        g_invdeg[i] = 1.0f / d;
        atomicAdd(&g_cnt[batch[i]], 1.0f);
    }
    __syncthreads();
    int cur = 0;
#pragma unroll
    for (int off = 1; off < 256; off <<= 1) {
        int val = s[cur][tid];
        if (tid >= off) val += s[cur][tid - off];
        s[cur ^ 1][tid] = val;
        cur ^= 1;
        __syncthreads();
    }
    if (tid == 0) blockoff = atomicAdd(&g_counter, s[cur][255]);
    __syncthreads();
    int excl = (tid == 0) ? 0 : s[cur][tid - 1];
    if (i < NN) {
        int rs = excl + blockoff;
        g_rowstart[i] = rs;
        g_cursor[i] = rs;
    }
}

__global__ void scatter_kernel(const int* __restrict__ src, const int* __restrict__ dst) {
    int e = blockIdx.x * blockDim.x + threadIdx.x;
    if (e < NE) {
        int d = dst[e];
        int pos = atomicAdd(&g_cursor[d], 1);
        g_ssorted[pos] = src[e];
    }
}

// ---------------- Tensor-core GEMM + self-loop init ----------------
// in = (FIRST ? x : relu(g_agg + b_prev)); a = in @ W (fp16 in, fp32 accum)
// g_hh = half(a * dinv); g_agg = a * invdeg
// Block: 128 threads = 4 warps; each warp owns 16 nodes (M=16), N=64, K=64.
// mma.sync.m16n8k16: 4 k-tiles (A frags held in regs) x 8 n-tiles.
#define XS_STRIDE 66   // 64 + 2 halfs padding (bank-conflict mitigation)

template <bool FIRST>
__global__ __launch_bounds__(128) void gemm_tc_kernel(const float* __restrict__ x,
                                                      const float* __restrict__ W,
                                                      const float* __restrict__ bprev) {
    __shared__ __half Wt[F * XS_STRIDE];        // Wt[n][k] = W[k][n]  (B, col-major)
    __shared__ __half Xs[4][16 * XS_STRIDE];    // per-warp A tile [16 rows][64 k]

    int tid = threadIdx.x;
    // stage W transposed -> fp16
    for (int i = tid; i < F * F; i += 128) {
        int k = i >> 6, n = i & 63;
        Wt[n * XS_STRIDE + k] = __float2half(W[i]);   // W[i] = W[k][n]
    }

    int warp = tid >> 5, lane = tid & 31;
    int gid = lane >> 2, tig = lane & 3;
    int nodebase = blockIdx.x * 64 + warp * 16;

    // stage this warp's 16 input rows (bias+relu fused) -> fp16
    const float4* in4 = FIRST ? (const float4*)x : (const float4*)g_agg;
    const float4* b4 = (const float4*)bprev;
    int hl = lane >> 4;     // row-in-pair
    int qi = lane & 15;     // float4 index within row
    __half* Xw = Xs[warp];
#pragma unroll
    for (int rr = 0; rr < 8; ++rr) {
        int r = rr * 2 + hl;
        int node = nodebase + r;
        float4 xv = make_float4(0.f, 0.f, 0.f, 0.f);
        if (node < NN) {
            xv = in4[(size_t)node * 16 + qi];
            if (!FIRST) {
                float4 bv = b4[qi];
                xv.x = fmaxf(xv.x + bv.x, 0.f);
                xv.y = fmaxf(xv.y + bv.y, 0.f);
                xv.z = fmaxf(xv.z + bv.z, 0.f);
                xv.w = fmaxf(xv.w + bv.w, 0.f);
            }
        }
        __half2* p = (__half2*)&Xw[r * XS_STRIDE + qi * 4];
        p[0] = __floats2half2_rn(xv.x, xv.y);
        p[1] = __floats2half2_rn(xv.z, xv.w);
    }
    __syncthreads();

    // A fragments for all 4 k-tiles (16 x b32 regs)
    unsigned a[4][4];
#pragma unroll
    for (int kt = 0; kt < 4; ++kt) {
        int kc = kt * 16 + tig * 2;
        a[kt][0] = *(const unsigned*)&Xw[gid * XS_STRIDE + kc];
        a[kt][1] = *(const unsigned*)&Xw[(gid + 8) * XS_STRIDE + kc];
        a[kt][2] = *(const unsigned*)&Xw[gid * XS_STRIDE + kc + 8];
        a[kt][3] = *(const unsigned*)&Xw[(gid + 8) * XS_STRIDE + kc + 8];
    }

    int row0 = nodebase + gid;
    int row1 = nodebase + gid + 8;
    float dv0 = 0.f, id0 = 0.f, dv1 = 0.f, id1 = 0.f;
    if (row0 < NN) { dv0 = g_dinv[row0]; id0 = g_invdeg[row0]; }
    if (row1 < NN) { dv1 = g_dinv[row1]; id1 = g_invdeg[row1]; }

#pragma unroll
    for (int nt = 0; nt < 8; ++nt) {
        float c0 = 0.f, c1 = 0.f, c2 = 0.f, c3 = 0.f;
        const __half* Wn = &Wt[(nt * 8 + gid) * XS_STRIDE];
#pragma unroll
        for (int kt = 0; kt < 4; ++kt) {
            int kc = kt * 16 + tig * 2;
            unsigned b0 = *(const unsigned*)&Wn[kc];
            unsigned b1 = *(const unsigned*)&Wn[kc + 8];
            asm volatile(
                "mma.sync.aligned.m16n8k16.row.col.f32.f16.f16.f32 "
                "{%0,%1,%2,%3}, {%4,%5,%6,%7}, {%8,%9}, {%0,%1,%2,%3};"
                : "+f"(c0), "+f"(c1), "+f"(c2), "+f"(c3)
                : "r"(a[kt][0]), "r"(a[kt][1]), "r"(a[kt][2]), "r"(a[kt][3]),
                  "r"(b0), "r"(b1));
        }
        int col = nt * 8 + tig * 2;
        if (row0 < NN) {
            *(__half2*)&g_hh[(size_t)row0 * F + col] = __floats2half2_rn(c0 * dv0, c1 * dv0);
            *(float2*)&g_agg[(size_t)row0 * F + col] = make_float2(c0 * id0, c1 * id0);
        }
        if (row1 < NN) {
            *(__half2*)&g_hh[(size_t)row1 * F + col] = __floats2half2_rn(c2 * dv1, c3 * dv1);
            *(float2*)&g_agg[(size_t)row1 * F + col] = make_float2(c2 * id1, c3 * id1);
        }
    }
}

// ---------------- CSR aggregation: 8-lane group per dst, fp16 gather, MLP=4 ----
template <bool LAST>
__global__ __launch_bounds__(256) void agg_kernel(const int* __restrict__ batch,
                                                  const float* __restrict__ b3) {
    int t = blockIdx.x * blockDim.x + threadIdx.x;
    int d = t >> 3;
    int l = t & 7;            // 8 lanes x 8 features (16B) per lane
    if (d >= NN) return;
    int start = g_rowstart[d];
    int n = g_deg[d];
    const uint4* h4 = (const uint4*)g_hh;   // one uint4 = 8 halfs

    float acc[8];
#pragma unroll
    for (int j = 0; j < 8; ++j) acc[j] = 0.f;

    int i = 0;
    for (; i + 4 <= n; i += 4) {
        int s0 = g_ssorted[start + i];
        int s1 = g_ssorted[start + i + 1];
        int s2 = g_ssorted[start + i + 2];
        int s3 = g_ssorted[start + i + 3];
        uint4 r0 = h4[(size_t)s0 * 8 + l];
        uint4 r1 = h4[(size_t)s1 * 8 + l];
        uint4 r2 = h4[(size_t)s2 * 8 + l];
        uint4 r3 = h4[(size_t)s3 * 8 + l];
        const __half2* p0 = (const __half2*)&r0;
        const __half2* p1 = (const __half2*)&r1;
        const __half2* p2 = (const __half2*)&r2;
        const __half2* p3 = (const __half2*)&r3;
#pragma unroll
        for (int j = 0; j < 4; ++j) {
            float2 f0 = __half22float2(p0[j]);
            float2 f1 = __half22float2(p1[j]);
            float2 f2 = __half22float2(p2[j]);
            float2 f3 = __half22float2(p3[j]);
            acc[j * 2 + 0] += (f0.x + f1.x) + (f2.x + f3.x);
            acc[j * 2 + 1] += (f0.y + f1.y) + (f2.y + f3.y);
        }
    }
    for (; i < n; ++i) {
        int s0 = g_ssorted[start + i];
        uint4 r0 = h4[(size_t)s0 * 8 + l];
        const __half2* p0 = (const __half2*)&r0;
#pragma unroll
        for (int j = 0; j < 4; ++j) {
            float2 f0 = __half22float2(p0[j]);
            acc[j * 2 + 0] += f0.x;
            acc[j * 2 + 1] += f0.y;
        }
    }

    float dd = g_dinv[d];
    float4* ar = (float4*)(g_agg + (size_t)d * F + l * 8);
    float4 s0v = ar[0];
    float4 s1v = ar[1];
    float4 o0 = make_float4(fmaf(acc[0], dd, s0v.x), fmaf(acc[1], dd, s0v.y),
                            fmaf(acc[2], dd, s0v.z), fmaf(acc[3], dd, s0v.w));
    float4 o1 = make_float4(fmaf(acc[4], dd, s1v.x), fmaf(acc[5], dd, s1v.y),
                            fmaf(acc[6], dd, s1v.z), fmaf(acc[7], dd, s1v.w));
    if (!LAST) {
        ar[0] = o0;
        ar[1] = o1;
    } else {
        float4 b0 = ((const float4*)b3)[l * 2 + 0];
        float4 b1 = ((const float4*)b3)[l * 2 + 1];
        o0.x = fmaxf(o0.x + b0.x, 0.f); o0.y = fmaxf(o0.y + b0.y, 0.f);
        o0.z = fmaxf(o0.z + b0.z, 0.f); o0.w = fmaxf(o0.w + b0.w, 0.f);
        o1.x = fmaxf(o1.x + b1.x, 0.f); o1.y = fmaxf(o1.y + b1.y, 0.f);
        o1.z = fmaxf(o1.z + b1.z, 0.f); o1.w = fmaxf(o1.w + b1.w, 0.f);
        int g = batch[d];
        red_add_v4(g_sums + (size_t)g * F + l * 8, o0);
        red_add_v4(g_sums + (size_t)g * F + l * 8 + 4, o1);
    }
}

// out[g] = (sums[g] . Wl) / max(cnt,1) + bl
__global__ void final_kernel(const float* __restrict__ Wl, const float* __restrict__ bl,
                             float* __restrict__ out) {
    int g = threadIdx.x;
    float c = fmaxf(g_cnt[g], 1.0f);
    float acc = 0.f;
#pragma unroll
    for (int f = 0; f < F; ++f) acc = fmaf(g_sums[g * F + f], Wl[f], acc);
    out[g] = acc / c + bl[0];
}

// ---------------- launch ----------------
extern "C" void kernel_launch(void* const* d_in, const int* in_sizes, int n_in,
                              void* d_out, int out_size) {
    const float* x   = (const float*)d_in[0];
    const int* src   = (const int*)d_in[1];
    const int* dst   = (const int*)d_in[2];
    const int* batch = (const int*)d_in[3];
    const float* W1 = (const float*)d_in[4];
    const float* b1 = (const float*)d_in[5];
    const float* W2 = (const float*)d_in[6];
    const float* b2 = (const float*)d_in[7];
    const float* W3 = (const float*)d_in[8];
    const float* b3 = (const float*)d_in[9];
    const float* Wl = (const float*)d_in[10];
    const float* bl = (const float*)d_in[11];
    float* out = (float*)d_out;

    const int NB_NODE = (NN + 255) / 256;        // 196
    const int NB_EDGE = (NE + 255) / 256;        // 3125
    const int NB_GEMM = (NN + 63) / 64;          // 782 (64 nodes per block)
    const int NB_AGG  = (NN * 8 + 255) / 256;    // 1563
    const int NB_ZERO = (NG * F + 255) / 256;    // 64

    void* deg_ptr = nullptr;
    cudaGetSymbolAddress(&deg_ptr, g_deg);
    cudaMemsetAsync(deg_ptr, 0, NN * sizeof(int));

    zero_kernel<<<NB_ZERO, 256>>>();
    deg_kernel<<<NB_EDGE, 256>>>(dst);
    scan_fused_kernel<<<NB_NODE, 256>>>(batch);
    scatter_kernel<<<NB_EDGE, 256>>>(src, dst);

    // layer 1
    gemm_tc_kernel<true><<<NB_GEMM, 128>>>(x, W1, nullptr);
    agg_kernel<false><<<NB_AGG, 256>>>(batch, b3);
    // layer 2
    gemm_tc_kernel<false><<<NB_GEMM, 128>>>(nullptr, W2, b1);
    agg_kernel<false><<<NB_AGG, 256>>>(batch, b3);
    // layer 3 (+ fused pool)
    gemm_tc_kernel<false><<<NB_GEMM, 128>>>(nullptr, W3, b2);
    agg_kernel<true><<<NB_AGG, 256>>>(batch, b3);

    final_kernel<<<1, 256>>>(Wl, bl, out);
}